// round 14
// baseline (speedup 1.0000x reference)
#include <cuda_runtime.h>
#include <cuda_fp16.h>
#include <math.h>
#include <stdint.h>

#define S_ALL 2304
#define STXT  256
#define SIMG  2048
#define DM    3072
#define NH    24
#define HD    128

// ---------------- scratch (static device globals; no runtime allocation) ----
__device__ __half g_X [S_ALL * DM];                // concat(enc,hid) fp16
__device__ __half g_Q [S_ALL * DM];                // fp16, pre-scaled log2e/sqrt(128)
__device__ __half g_K [S_ALL * DM];                // fp16 natural [s][d]
__device__ __half g_Vt[NH * HD * S_ALL];           // fp16 transposed [h][d][s]
__device__ __half g_O [S_ALL * DM];                // fp16
__device__ __half g_Wt[(size_t)8 * DM * DM];       // fp16 transposed weights [n][k]

__device__ __forceinline__ void cp16(void* dst, const void* src) {
    uint32_t s = (uint32_t)__cvta_generic_to_shared(dst);
    asm volatile("cp.async.cg.shared.global [%0], [%1], 16;" :: "r"(s), "l"(src));
}
#define CP_COMMIT() asm volatile("cp.async.commit_group;")
#define CP_WAIT1()  asm volatile("cp.async.wait_group 1;")
#define CP_WAIT0()  asm volatile("cp.async.wait_group 0;")

#define MMA16(d0,d1,d2,d3,a0,a1,a2,a3,b0,b1)                                  \
    asm("mma.sync.aligned.m16n8k16.row.col.f32.f16.f16.f32 "                  \
        "{%0,%1,%2,%3}, {%4,%5,%6,%7}, {%8,%9}, {%0,%1,%2,%3};"               \
        : "+f"(d0), "+f"(d1), "+f"(d2), "+f"(d3)                              \
        : "r"(a0), "r"(a1), "r"(a2), "r"(a3), "r"(b0), "r"(b1))

#define LDSM_X4(r0,r1,r2,r3,addr)                                             \
    asm volatile("ldmatrix.sync.aligned.m8n8.x4.shared.b16 {%0,%1,%2,%3}, [%4];" \
        : "=r"(r0), "=r"(r1), "=r"(r2), "=r"(r3) : "r"(addr))

__device__ __forceinline__ uint32_t sptr(const void* p) {
    return (uint32_t)__cvta_generic_to_shared(p);
}
__device__ __forceinline__ uint32_t pack_h2(float a, float b) {
    __half2 h = __floats2half2_rn(a, b);
    return *(uint32_t*)&h;
}
__device__ __forceinline__ float ex2(float x) {
    float r;
    asm("ex2.approx.f32 %0, %1;" : "=f"(r) : "f"(x));
    return r;
}

// ============================================================================
// fp16 GEMM core: 128x128 block, 8 warps (2x4), warp tile 64x32, k-chunk 64,
// 3-stage cp.async, ldmatrix frag loads, one syncthreads per chunk,
// unroll-3 main loop (static stage indices).
// ============================================================================

#define PH 72
#define PE 132
#define NSTG 3
#define GEMM_SMEM (NSTG * 2 * 128 * PH * 2)

__device__ __forceinline__ void gemm_core_h(
    const __half* __restrict__ A, const __half* __restrict__ B,
    float acc[4][4][4])
{
    extern __shared__ char dsraw[];
    __half* AsB = (__half*)dsraw;
    __half* BsB = AsB + NSTG * 128 * PH;

    const int tid  = threadIdx.x;
    const int warp = tid >> 5, lane = tid & 31;
    const int wm = (warp >> 2) * 64;
    const int wn = (warp & 3)  * 32;
    const int l16 = lane & 15;
    const int lh  = (lane >> 4) << 3;

#pragma unroll
    for (int mt = 0; mt < 4; mt++)
#pragma unroll
        for (int nt = 0; nt < 4; nt++)
#pragma unroll
            for (int r = 0; r < 4; r++) acc[mt][nt][r] = 0.f;

    const int srow = tid >> 1;
    const int soff = (tid & 1) * 32;

    auto issue = [&](int k0, int stage) {
        const __half* Ag = A + (size_t)srow * DM + k0 + soff;
        __half* Ad = AsB + stage * 128 * PH + srow * PH + soff;
#pragma unroll
        for (int i = 0; i < 4; i++) cp16(Ad + i * 8, Ag + i * 8);
        const __half* Bg = B + (size_t)srow * DM + k0 + soff;
        __half* Bd = BsB + stage * 128 * PH + srow * PH + soff;
#pragma unroll
        for (int i = 0; i < 4; i++) cp16(Bd + i * 8, Bg + i * 8);
        CP_COMMIT();
    };

    const int ntile = DM / 64;   // 48 (divisible by NSTG=3 -> clean unroll)
    issue(0, 0);
    issue(64, 1);

#pragma unroll 3
    for (int t = 0; t < ntile; t++) {
        const int cur = t % NSTG;
        if (t + 1 < ntile) { CP_WAIT1(); } else { CP_WAIT0(); }
        __syncthreads();
        if (t + 2 < ntile) issue((t + 2) * 64, (t + 2) % NSTG);

        const __half* As = AsB + cur * 128 * PH;
        const __half* Bs = BsB + cur * 128 * PH;

#pragma unroll
        for (int kk = 0; kk < 64; kk += 16) {
            uint32_t a[4][4], b[4][2];
#pragma unroll
            for (int mt = 0; mt < 4; mt++) {
                uint32_t ad = sptr(&As[(wm + mt * 16 + l16) * PH + kk + lh]);
                LDSM_X4(a[mt][0], a[mt][1], a[mt][2], a[mt][3], ad);
            }
#pragma unroll
            for (int nt = 0; nt < 4; nt += 2) {
                uint32_t bd = sptr(&Bs[(wn + nt * 8 + l16) * PH + kk + lh]);
                LDSM_X4(b[nt][0], b[nt + 1][0], b[nt][1], b[nt + 1][1], bd);
            }
#pragma unroll
            for (int mt = 0; mt < 4; mt++)
#pragma unroll
                for (int nt = 0; nt < 4; nt++)
                    MMA16(acc[mt][nt][0], acc[mt][nt][1], acc[mt][nt][2], acc[mt][nt][3],
                          a[mt][0], a[mt][1], a[mt][2], a[mt][3],
                          b[nt][0], b[nt][1]);
        }
    }
    __syncthreads();
}

// ---- pre-pass: concat + fp16-convert activations ----------------------------
__global__ __launch_bounds__(256) void k_round_act(
    const float* __restrict__ hid, const float* __restrict__ enc)
{
    const int total = S_ALL * DM / 4;
    for (int i = blockIdx.x * blockDim.x + threadIdx.x; i < total;
         i += gridDim.x * blockDim.x) {
        int r = (i * 4) / DM, c = (i * 4) % DM;
        const float* s = (r < STXT) ? enc + (size_t)r * DM + c
                                    : hid + (size_t)(r - STXT) * DM + c;
        float4 v = *(const float4*)s;
        uint2 o;
        o.x = pack_h2(v.x, v.y);
        o.y = pack_h2(v.z, v.w);
        *(uint2*)&g_X[(size_t)i * 4] = o;
    }
}

// ---- pre-pass: transpose + fp16-convert the 8 weight matrices ---------------
__global__ __launch_bounds__(256) void k_transw(
    const float* __restrict__ w0, const float* __restrict__ w1,
    const float* __restrict__ w2, const float* __restrict__ w3,
    const float* __restrict__ w4, const float* __restrict__ w5,
    const float* __restrict__ w6, const float* __restrict__ w7)
{
    __shared__ float t[32][33];
    const float* W =
        (blockIdx.z == 0) ? w0 : (blockIdx.z == 1) ? w1 : (blockIdx.z == 2) ? w2 :
        (blockIdx.z == 3) ? w3 : (blockIdx.z == 4) ? w4 : (blockIdx.z == 5) ? w5 :
        (blockIdx.z == 6) ? w6 : w7;
    __half* Wt = g_Wt + (size_t)blockIdx.z * DM * DM;

    const int bx = blockIdx.x * 32;
    const int by = blockIdx.y * 32;
    const int tx = threadIdx.x & 31, ty = threadIdx.x >> 5;

#pragma unroll
    for (int j = ty; j < 32; j += 8)
        t[j][tx] = W[(size_t)(by + j) * DM + bx + tx];
    __syncthreads();
#pragma unroll
    for (int j = ty; j < 32; j += 8)
        Wt[(size_t)(bx + j) * DM + by + tx] = __float2half_rn(t[tx][j]);
}

// ---- QKV projection + fused RMSNorm/RoPE epilogue (fp16 outputs) ------------
__global__ __launch_bounds__(256, 2) void k_qkv(
    const float* __restrict__ bqa, const float* __restrict__ bka,
    const float* __restrict__ bva,
    const float* __restrict__ nq,  const float* __restrict__ naq,
    const float* __restrict__ nk,  const float* __restrict__ nak,
    const float* __restrict__ cosb, const float* __restrict__ sinb)
{
    extern __shared__ char dsraw[];
    const int which = blockIdx.z;
    const float* badd = (which == 0) ? bqa : (which == 1) ? bka : bva;

    const int n0 = blockIdx.x * 128;
    const int m0 = blockIdx.y * 128;
    const bool is_enc = (m0 < STXT);
    const int slot = which + (is_enc ? 3 : 0);

    const __half* A = g_X + (size_t)m0 * DM;
    const __half* B = g_Wt + (size_t)slot * DM * DM + (size_t)n0 * DM;

    float acc[4][4][4];
    gemm_core_h(A, B, acc);

    const int tid  = threadIdx.x;
    const int warp = tid >> 5, lane = tid & 31;
    const int wm = (warp >> 2) * 64;
    const int wn = (warp & 3)  * 32;
    const int lr = lane >> 2, lc = lane & 3;

    float* Es = (float*)dsraw;  // 128 x PE
#pragma unroll
    for (int mt = 0; mt < 4; mt++) {
        int row = wm + mt * 16 + lr;
#pragma unroll
        for (int nt = 0; nt < 4; nt++) {
            int col = wn + nt * 8 + 2 * lc;
            float b0 = is_enc ? badd[n0 + col]     : 0.f;
            float b1 = is_enc ? badd[n0 + col + 1] : 0.f;
            float2 lo = make_float2(acc[mt][nt][0] + b0, acc[mt][nt][1] + b1);
            float2 hi = make_float2(acc[mt][nt][2] + b0, acc[mt][nt][3] + b1);
            *(float2*)&Es[row * PE + col]       = lo;
            *(float2*)&Es[(row + 8) * PE + col] = hi;
        }
    }
    __syncthreads();

    if (which == 2) {
        const int h = blockIdx.x;
        const int d  = tid >> 1;
        const int ms = (tid & 1) * 64;
        __half* dstv = g_Vt + ((size_t)h * HD + d) * S_ALL + m0 + ms;
#pragma unroll
        for (int j = 0; j < 64; j += 2) {
            float v0 = Es[(ms + j)     * PE + d];
            float v1 = Es[(ms + j + 1) * PE + d];
            *(uint32_t*)&dstv[j] = pack_h2(v0, v1);
        }
        return;
    }

    const float* gm = is_enc ? (which == 0 ? naq : nak)
                             : (which == 0 ? nq  : nk);
    __half* dst = (which == 0) ? g_Q : g_K;
    const float mult = (which == 0)
        ? 0.088388347648318447f * 1.4426950408889634f : 1.0f;

    const int row   = tid >> 1;
    const int cbase = (tid & 1) * 64;
    const int r     = m0 + row;

    float ss = 0.f;
#pragma unroll
    for (int i = 0; i < 64; i += 4) {
        float4 v = *(float4*)&Es[row * PE + cbase + i];
        ss += v.x * v.x + v.y * v.y + v.z * v.z + v.w * v.w;
    }
    ss += __shfl_xor_sync(0xffffffffu, ss, 1);
    float rs = rsqrtf(ss * (1.0f / HD) + 1e-6f);

#pragma unroll
    for (int i = 0; i < 64; i += 4) {
        int d = cbase + i;
        float4 v = *(float4*)&Es[row * PE + d];
        float4 g = *(const float4*)&gm[d];
        float4 c = *(const float4*)&cosb[r * HD + d];
        float4 s = *(const float4*)&sinb[r * HD + d];
        float x0 = v.x * rs * g.x, x1 = v.y * rs * g.y;
        float x2 = v.z * rs * g.z, x3 = v.w * rs * g.w;
        uint2 o;
        o.x = pack_h2((x0 * c.x - x1 * s.x) * mult, (x1 * c.y + x0 * s.y) * mult);
        o.y = pack_h2((x2 * c.z - x3 * s.z) * mult, (x3 * c.w + x2 * s.w) * mult);
        *(uint2*)&dst[(size_t)r * DM + n0 + d] = o;
    }
}

// ============================================================================
// Fused flash attention, fp16 mma + ldmatrix + ex2 softmax.
// l-reduction deferred past the PV mma burst; unroll-2 chunk loop.
// ============================================================================

#define PQ 136
#define PVT 72
#define FLASH_SMEM (128*PQ*2 + 2*64*PQ*2 + 2*128*PVT*2)

__global__ __launch_bounds__(256, 2) void k_flash()
{
    extern __shared__ char smraw[];
    __half* Qs  = (__half*)smraw;
    __half* KsB = Qs + 128 * PQ;
    __half* VsB = KsB + 2 * 64 * PQ;

    const int tid  = threadIdx.x;
    const int warp = tid >> 5, lane = tid & 31;
    const int l16 = lane & 15;
    const int lh  = (lane >> 4) << 3;
    const int h  = blockIdx.y;
    const int m0 = blockIdx.x * 128;

    auto issue_chunk = [&](int c, int stage) {
        const int s0 = c * 64;
        __half* Kd = KsB + stage * 64 * PQ;
        __half* Vd = VsB + stage * 128 * PVT;
#pragma unroll
        for (int q = 0; q < 4; q++) {
            int idx = tid + q * 256;
            {
                int row = idx >> 4, off = (idx & 15) * 8;
                cp16(Kd + row * PQ + off,
                     g_K + (size_t)(s0 + row) * DM + h * HD + off);
            }
            {
                int row = idx >> 3, off = (idx & 7) * 8;
                cp16(Vd + row * PVT + off,
                     g_Vt + ((size_t)h * HD + row) * S_ALL + s0 + off);
            }
        }
        CP_COMMIT();
    };

#pragma unroll
    for (int q = 0; q < 8; q++) {
        int idx = tid + q * 256;
        int row = idx >> 4, off = (idx & 15) * 8;
        cp16(Qs + row * PQ + off, g_Q + (size_t)(m0 + row) * DM + h * HD + off);
    }
    issue_chunk(0, 0);

    float m_r0 = -1e30f, m_r1 = -1e30f;
    float l_r0 = 0.f,    l_r1 = 0.f;
    float O[16][4];
#pragma unroll
    for (int i = 0; i < 16; i++)
#pragma unroll
        for (int j = 0; j < 4; j++) O[i][j] = 0.f;

    const int rb = warp * 16;
    const int NCH = S_ALL / 64;

#pragma unroll 2
    for (int c = 0; c < NCH; c++) {
        const int cur = c & 1;
        CP_WAIT0();
        __syncthreads();
        if (c + 1 < NCH) issue_chunk(c + 1, cur ^ 1);

        const __half* Ks = KsB + cur * 64 * PQ;
        const __half* Vs = VsB + cur * 128 * PVT;

        // ---- S' = (Q*log2e/sqrt(d)) K^T
        float sacc[8][4];
#pragma unroll
        for (int nt = 0; nt < 8; nt++)
#pragma unroll
            for (int r = 0; r < 4; r++) sacc[nt][r] = 0.f;

#pragma unroll
        for (int kk = 0; kk < HD; kk += 16) {
            uint32_t a0, a1, a2, a3;
            uint32_t qa = sptr(&Qs[(rb + l16) * PQ + kk + lh]);
            LDSM_X4(a0, a1, a2, a3, qa);
            uint32_t b[8][2];
#pragma unroll
            for (int nt = 0; nt < 8; nt += 2) {
                uint32_t kd = sptr(&Ks[(nt * 8 + l16) * PQ + kk + lh]);
                LDSM_X4(b[nt][0], b[nt + 1][0], b[nt][1], b[nt + 1][1], kd);
            }
#pragma unroll
            for (int nt = 0; nt < 8; nt++)
                MMA16(sacc[nt][0], sacc[nt][1], sacc[nt][2], sacc[nt][3],
                      a0, a1, a2, a3, b[nt][0], b[nt][1]);
        }

        // ---- online softmax (base-2): max reduction + exp only
        float cm0 = -1e30f, cm1 = -1e30f;
#pragma unroll
        for (int nt = 0; nt < 8; nt++) {
            cm0 = fmaxf(cm0, fmaxf(sacc[nt][0], sacc[nt][1]));
            cm1 = fmaxf(cm1, fmaxf(sacc[nt][2], sacc[nt][3]));
        }
        cm0 = fmaxf(cm0, __shfl_xor_sync(0xffffffffu, cm0, 1));
        cm0 = fmaxf(cm0, __shfl_xor_sync(0xffffffffu, cm0, 2));
        cm1 = fmaxf(cm1, __shfl_xor_sync(0xffffffffu, cm1, 1));
        cm1 = fmaxf(cm1, __shfl_xor_sync(0xffffffffu, cm1, 2));

        float mn0 = fmaxf(m_r0, cm0), mn1 = fmaxf(m_r1, cm1);
        float al0 = ex2(m_r0 - mn0), al1 = ex2(m_r1 - mn1);
        m_r0 = mn0; m_r1 = mn1;

        uint32_t ph[8][2];
        float cs0 = 0.f, cs1 = 0.f;
#pragma unroll
        for (int nt = 0; nt < 8; nt++) {
            float p0 = ex2(sacc[nt][0] - mn0);
            float p1 = ex2(sacc[nt][1] - mn0);
            float p2 = ex2(sacc[nt][2] - mn1);
            float p3 = ex2(sacc[nt][3] - mn1);
            ph[nt][0] = pack_h2(p0, p1);
            ph[nt][1] = pack_h2(p2, p3);
            cs0 += p0 + p1;
            cs1 += p2 + p3;
        }

#pragma unroll
        for (int nt2 = 0; nt2 < 16; nt2++) {
            O[nt2][0] *= al0; O[nt2][1] *= al0;
            O[nt2][2] *= al1; O[nt2][3] *= al1;
        }

        // ---- O += P V (l-reduction deferred past this mma burst)
#pragma unroll
        for (int ks = 0; ks < 4; ks++) {
            uint32_t a0 = ph[2 * ks][0];
            uint32_t a1 = ph[2 * ks][1];
            uint32_t a2 = ph[2 * ks + 1][0];
            uint32_t a3 = ph[2 * ks + 1][1];
#pragma unroll
            for (int nt2 = 0; nt2 < 16; nt2 += 2) {
                uint32_t b0, b1, b2, b3;
                uint32_t vd = sptr(&Vs[(nt2 * 8 + l16) * PVT + ks * 16 + lh]);
                LDSM_X4(b0, b1, b2, b3, vd);
                MMA16(O[nt2][0], O[nt2][1], O[nt2][2], O[nt2][3],
                      a0, a1, a2, a3, b0, b2);
                MMA16(O[nt2 + 1][0], O[nt2 + 1][1], O[nt2 + 1][2], O[nt2 + 1][3],
                      a0, a1, a2, a3, b1, b3);
            }
        }

        // ---- deferred l reduction (off the tensor critical path)
        cs0 += __shfl_xor_sync(0xffffffffu, cs0, 1);
        cs0 += __shfl_xor_sync(0xffffffffu, cs0, 2);
        cs1 += __shfl_xor_sync(0xffffffffu, cs1, 1);
        cs1 += __shfl_xor_sync(0xffffffffu, cs1, 2);
        l_r0 = l_r0 * al0 + cs0;
        l_r1 = l_r1 * al1 + cs1;
    }

    // ---- epilogue
    const int lr = lane >> 2, lc = lane & 3;
    float i0 = 1.0f / l_r0, i1 = 1.0f / l_r1;
    const int row0 = m0 + rb + lr;
#pragma unroll
    for (int nt2 = 0; nt2 < 16; nt2++) {
        int col = h * HD + nt2 * 8 + 2 * lc;
        *(uint32_t*)&g_O[(size_t)row0 * DM + col] =
            pack_h2(O[nt2][0] * i0, O[nt2][1] * i0);
        *(uint32_t*)&g_O[(size_t)(row0 + 8) * DM + col] =
            pack_h2(O[nt2][2] * i1, O[nt2][3] * i1);
    }
}

// ---- output projections ------------------------------------------------------
__global__ __launch_bounds__(256, 2) void k_outproj(
    const float* __restrict__ b_out, const float* __restrict__ b_ao,
    float* __restrict__ outbuf)
{
    const int n0 = blockIdx.x * 128;
    const int m0 = blockIdx.y * 128;
    const bool is_enc = (m0 < STXT);
    const __half* B = g_Wt + (size_t)(is_enc ? 7 : 6) * DM * DM + (size_t)n0 * DM;
    const float* bias = (is_enc ? b_ao : b_out) + n0;
    float* out = is_enc ? (outbuf + (size_t)SIMG * DM + (size_t)m0 * DM)
                        : (outbuf + (size_t)(m0 - STXT) * DM);

    float acc[4][4][4];
    gemm_core_h(g_O + (size_t)m0 * DM, B, acc);

    const int tid  = threadIdx.x;
    const int warp = tid >> 5, lane = tid & 31;
    const int wm = (warp >> 2) * 64;
    const int wn = (warp & 3)  * 32;
    const int lr = lane >> 2, lc = lane & 3;

#pragma unroll
    for (int mt = 0; mt < 4; mt++) {
        int row = wm + mt * 16 + lr;
#pragma unroll
        for (int nt = 0; nt < 4; nt++) {
            int col = wn + nt * 8 + 2 * lc;
            float b0 = bias[col];
            float b1 = bias[col + 1];
            float2 lo = make_float2(acc[mt][nt][0] + b0, acc[mt][nt][1] + b1);
            float2 hi = make_float2(acc[mt][nt][2] + b0, acc[mt][nt][3] + b1);
            *(float2*)&out[(size_t)row * DM + n0 + col]       = lo;
            *(float2*)&out[(size_t)(row + 8) * DM + n0 + col] = hi;
        }
    }
}

// ============================================================================
extern "C" void kernel_launch(void* const* d_in, const int* in_sizes, int n_in,
                              void* d_out, int out_size)
{
    const float* hid  = (const float*)d_in[0];
    const float* enc  = (const float*)d_in[1];
    const float* cosb = (const float*)d_in[2];
    const float* sinb = (const float*)d_in[3];
    const float* wq   = (const float*)d_in[4];
    const float* wk   = (const float*)d_in[5];
    const float* wv   = (const float*)d_in[6];
    const float* wqa  = (const float*)d_in[7];
    const float* wka  = (const float*)d_in[8];
    const float* wva  = (const float*)d_in[9];
    const float* bqa  = (const float*)d_in[10];
    const float* bka  = (const float*)d_in[11];
    const float* bva  = (const float*)d_in[12];
    const float* nq   = (const float*)d_in[13];
    const float* nk   = (const float*)d_in[14];
    const float* naq  = (const float*)d_in[15];
    const float* nak  = (const float*)d_in[16];
    const float* wout = (const float*)d_in[17];
    const float* bout = (const float*)d_in[18];
    const float* wao  = (const float*)d_in[19];
    const float* bao  = (const float*)d_in[20];
    float* out = (float*)d_out;

    cudaFuncSetAttribute(k_qkv,     cudaFuncAttributeMaxDynamicSharedMemorySize, GEMM_SMEM);
    cudaFuncSetAttribute(k_outproj, cudaFuncAttributeMaxDynamicSharedMemorySize, GEMM_SMEM);
    cudaFuncSetAttribute(k_flash,   cudaFuncAttributeMaxDynamicSharedMemorySize, FLASH_SMEM);

    k_round_act<<<512, 256>>>(hid, enc);
    dim3 tw_grid(DM / 32, DM / 32, 8);
    k_transw<<<tw_grid, 256>>>(wq, wk, wv, wqa, wka, wva, wout, wao);

    dim3 qkv_grid(DM / 128, S_ALL / 128, 3);        // 24 x 18 x 3
    k_qkv<<<qkv_grid, 256, GEMM_SMEM>>>(bqa, bka, bva,
                                        nq, naq, nk, nak, cosb, sinb);

    dim3 fl_grid(S_ALL / 128, NH);                  // 18 x 24
    k_flash<<<fl_grid, 256, FLASH_SMEM>>>();

    dim3 gemm_grid(DM / 128, S_ALL / 128);          // 24 x 18
    k_outproj<<<gemm_grid, 256, GEMM_SMEM>>>(bout, bao, out);
}

// round 15
// speedup vs baseline: 1.0197x; 1.0197x over previous
#include <cuda_runtime.h>
#include <cuda_fp16.h>
#include <math.h>
#include <stdint.h>

#define S_ALL 2304
#define STXT  256
#define SIMG  2048
#define DM    3072
#define NH    24
#define HD    128

// ---------------- scratch (static device globals; no runtime allocation) ----
__device__ __half g_X [S_ALL * DM];                // concat(enc,hid) fp16
__device__ __half g_Q [S_ALL * DM];                // fp16, pre-scaled log2e/sqrt(128)
__device__ __half g_K [S_ALL * DM];                // fp16 natural [s][d]
__device__ __half g_Vt[NH * HD * S_ALL];           // fp16 transposed [h][d][s]
__device__ __half g_O [S_ALL * DM];                // fp16
__device__ __half g_Wt[(size_t)8 * DM * DM];       // fp16 transposed weights [n][k]

__device__ __forceinline__ void cp16(void* dst, const void* src) {
    uint32_t s = (uint32_t)__cvta_generic_to_shared(dst);
    asm volatile("cp.async.cg.shared.global [%0], [%1], 16;" :: "r"(s), "l"(src));
}
#define CP_COMMIT() asm volatile("cp.async.commit_group;")
#define CP_WAIT1()  asm volatile("cp.async.wait_group 1;")
#define CP_WAIT0()  asm volatile("cp.async.wait_group 0;")

#define MMA16(d0,d1,d2,d3,a0,a1,a2,a3,b0,b1)                                  \
    asm("mma.sync.aligned.m16n8k16.row.col.f32.f16.f16.f32 "                  \
        "{%0,%1,%2,%3}, {%4,%5,%6,%7}, {%8,%9}, {%0,%1,%2,%3};"               \
        : "+f"(d0), "+f"(d1), "+f"(d2), "+f"(d3)                              \
        : "r"(a0), "r"(a1), "r"(a2), "r"(a3), "r"(b0), "r"(b1))

#define LDSM_X4(r0,r1,r2,r3,addr)                                             \
    asm volatile("ldmatrix.sync.aligned.m8n8.x4.shared.b16 {%0,%1,%2,%3}, [%4];" \
        : "=r"(r0), "=r"(r1), "=r"(r2), "=r"(r3) : "r"(addr))

__device__ __forceinline__ uint32_t sptr(const void* p) {
    return (uint32_t)__cvta_generic_to_shared(p);
}
__device__ __forceinline__ uint32_t pack_h2(float a, float b) {
    __half2 h = __floats2half2_rn(a, b);
    return *(uint32_t*)&h;
}
__device__ __forceinline__ float ex2(float x) {
    float r;
    asm("ex2.approx.f32 %0, %1;" : "=f"(r) : "f"(x));
    return r;
}

// ============================================================================
// fp16 GEMM core: 128x128 block, 8 warps (2x4), warp tile 64x32, k-chunk 64,
// 3-stage cp.async, ldmatrix frag loads, one syncthreads per chunk,
// unroll-3 main loop (static stage indices).  [R14 version — measured good]
// ============================================================================

#define PH 72
#define PE 132
#define NSTG 3
#define GEMM_SMEM (NSTG * 2 * 128 * PH * 2)

__device__ __forceinline__ void gemm_core_h(
    const __half* __restrict__ A, const __half* __restrict__ B,
    float acc[4][4][4])
{
    extern __shared__ char dsraw[];
    __half* AsB = (__half*)dsraw;
    __half* BsB = AsB + NSTG * 128 * PH;

    const int tid  = threadIdx.x;
    const int warp = tid >> 5, lane = tid & 31;
    const int wm = (warp >> 2) * 64;
    const int wn = (warp & 3)  * 32;
    const int l16 = lane & 15;
    const int lh  = (lane >> 4) << 3;

#pragma unroll
    for (int mt = 0; mt < 4; mt++)
#pragma unroll
        for (int nt = 0; nt < 4; nt++)
#pragma unroll
            for (int r = 0; r < 4; r++) acc[mt][nt][r] = 0.f;

    const int srow = tid >> 1;
    const int soff = (tid & 1) * 32;

    auto issue = [&](int k0, int stage) {
        const __half* Ag = A + (size_t)srow * DM + k0 + soff;
        __half* Ad = AsB + stage * 128 * PH + srow * PH + soff;
#pragma unroll
        for (int i = 0; i < 4; i++) cp16(Ad + i * 8, Ag + i * 8);
        const __half* Bg = B + (size_t)srow * DM + k0 + soff;
        __half* Bd = BsB + stage * 128 * PH + srow * PH + soff;
#pragma unroll
        for (int i = 0; i < 4; i++) cp16(Bd + i * 8, Bg + i * 8);
        CP_COMMIT();
    };

    const int ntile = DM / 64;   // 48 (divisible by 3 -> clean unroll)
    issue(0, 0);
    issue(64, 1);

#pragma unroll 3
    for (int t = 0; t < ntile; t++) {
        const int cur = t % NSTG;
        if (t + 1 < ntile) { CP_WAIT1(); } else { CP_WAIT0(); }
        __syncthreads();
        if (t + 2 < ntile) issue((t + 2) * 64, (t + 2) % NSTG);

        const __half* As = AsB + cur * 128 * PH;
        const __half* Bs = BsB + cur * 128 * PH;

#pragma unroll
        for (int kk = 0; kk < 64; kk += 16) {
            uint32_t a[4][4], b[4][2];
#pragma unroll
            for (int mt = 0; mt < 4; mt++) {
                uint32_t ad = sptr(&As[(wm + mt * 16 + l16) * PH + kk + lh]);
                LDSM_X4(a[mt][0], a[mt][1], a[mt][2], a[mt][3], ad);
            }
#pragma unroll
            for (int nt = 0; nt < 4; nt += 2) {
                uint32_t bd = sptr(&Bs[(wn + nt * 8 + l16) * PH + kk + lh]);
                LDSM_X4(b[nt][0], b[nt + 1][0], b[nt][1], b[nt + 1][1], bd);
            }
#pragma unroll
            for (int mt = 0; mt < 4; mt++)
#pragma unroll
                for (int nt = 0; nt < 4; nt++)
                    MMA16(acc[mt][nt][0], acc[mt][nt][1], acc[mt][nt][2], acc[mt][nt][3],
                          a[mt][0], a[mt][1], a[mt][2], a[mt][3],
                          b[nt][0], b[nt][1]);
        }
    }
    __syncthreads();
}

// ---- pre-pass: concat + fp16-convert activations ----------------------------
__global__ __launch_bounds__(256) void k_round_act(
    const float* __restrict__ hid, const float* __restrict__ enc)
{
    const int total = S_ALL * DM / 4;
    for (int i = blockIdx.x * blockDim.x + threadIdx.x; i < total;
         i += gridDim.x * blockDim.x) {
        int r = (i * 4) / DM, c = (i * 4) % DM;
        const float* s = (r < STXT) ? enc + (size_t)r * DM + c
                                    : hid + (size_t)(r - STXT) * DM + c;
        float4 v = *(const float4*)s;
        uint2 o;
        o.x = pack_h2(v.x, v.y);
        o.y = pack_h2(v.z, v.w);
        *(uint2*)&g_X[(size_t)i * 4] = o;
    }
}

// ---- pre-pass: transpose + fp16-convert the 8 weight matrices ---------------
__global__ __launch_bounds__(256) void k_transw(
    const float* __restrict__ w0, const float* __restrict__ w1,
    const float* __restrict__ w2, const float* __restrict__ w3,
    const float* __restrict__ w4, const float* __restrict__ w5,
    const float* __restrict__ w6, const float* __restrict__ w7)
{
    __shared__ float t[32][33];
    const float* W =
        (blockIdx.z == 0) ? w0 : (blockIdx.z == 1) ? w1 : (blockIdx.z == 2) ? w2 :
        (blockIdx.z == 3) ? w3 : (blockIdx.z == 4) ? w4 : (blockIdx.z == 5) ? w5 :
        (blockIdx.z == 6) ? w6 : w7;
    __half* Wt = g_Wt + (size_t)blockIdx.z * DM * DM;

    const int bx = blockIdx.x * 32;
    const int by = blockIdx.y * 32;
    const int tx = threadIdx.x & 31, ty = threadIdx.x >> 5;

#pragma unroll
    for (int j = ty; j < 32; j += 8)
        t[j][tx] = W[(size_t)(by + j) * DM + bx + tx];
    __syncthreads();
#pragma unroll
    for (int j = ty; j < 32; j += 8)
        Wt[(size_t)(bx + j) * DM + by + tx] = __float2half_rn(t[tx][j]);
}

// ---- QKV projection + fused RMSNorm/RoPE epilogue (fp16 outputs) ------------
__global__ __launch_bounds__(256, 2) void k_qkv(
    const float* __restrict__ bqa, const float* __restrict__ bka,
    const float* __restrict__ bva,
    const float* __restrict__ nq,  const float* __restrict__ naq,
    const float* __restrict__ nk,  const float* __restrict__ nak,
    const float* __restrict__ cosb, const float* __restrict__ sinb)
{
    extern __shared__ char dsraw[];
    const int which = blockIdx.z;
    const float* badd = (which == 0) ? bqa : (which == 1) ? bka : bva;

    const int n0 = blockIdx.x * 128;
    const int m0 = blockIdx.y * 128;
    const bool is_enc = (m0 < STXT);
    const int slot = which + (is_enc ? 3 : 0);

    const __half* A = g_X + (size_t)m0 * DM;
    const __half* B = g_Wt + (size_t)slot * DM * DM + (size_t)n0 * DM;

    float acc[4][4][4];
    gemm_core_h(A, B, acc);

    const int tid  = threadIdx.x;
    const int warp = tid >> 5, lane = tid & 31;
    const int wm = (warp >> 2) * 64;
    const int wn = (warp & 3)  * 32;
    const int lr = lane >> 2, lc = lane & 3;

    float* Es = (float*)dsraw;  // 128 x PE
#pragma unroll
    for (int mt = 0; mt < 4; mt++) {
        int row = wm + mt * 16 + lr;
#pragma unroll
        for (int nt = 0; nt < 4; nt++) {
            int col = wn + nt * 8 + 2 * lc;
            float b0 = is_enc ? badd[n0 + col]     : 0.f;
            float b1 = is_enc ? badd[n0 + col + 1] : 0.f;
            float2 lo = make_float2(acc[mt][nt][0] + b0, acc[mt][nt][1] + b1);
            float2 hi = make_float2(acc[mt][nt][2] + b0, acc[mt][nt][3] + b1);
            *(float2*)&Es[row * PE + col]       = lo;
            *(float2*)&Es[(row + 8) * PE + col] = hi;
        }
    }
    __syncthreads();

    if (which == 2) {
        const int h = blockIdx.x;
        const int d  = tid >> 1;
        const int ms = (tid & 1) * 64;
        __half* dstv = g_Vt + ((size_t)h * HD + d) * S_ALL + m0 + ms;
#pragma unroll
        for (int j = 0; j < 64; j += 2) {
            float v0 = Es[(ms + j)     * PE + d];
            float v1 = Es[(ms + j + 1) * PE + d];
            *(uint32_t*)&dstv[j] = pack_h2(v0, v1);
        }
        return;
    }

    const float* gm = is_enc ? (which == 0 ? naq : nak)
                             : (which == 0 ? nq  : nk);
    __half* dst = (which == 0) ? g_Q : g_K;
    const float mult = (which == 0)
        ? 0.088388347648318447f * 1.4426950408889634f : 1.0f;

    const int row   = tid >> 1;
    const int cbase = (tid & 1) * 64;
    const int r     = m0 + row;

    float ss = 0.f;
#pragma unroll
    for (int i = 0; i < 64; i += 4) {
        float4 v = *(float4*)&Es[row * PE + cbase + i];
        ss += v.x * v.x + v.y * v.y + v.z * v.z + v.w * v.w;
    }
    ss += __shfl_xor_sync(0xffffffffu, ss, 1);
    float rs = rsqrtf(ss * (1.0f / HD) + 1e-6f);

#pragma unroll
    for (int i = 0; i < 64; i += 4) {
        int d = cbase + i;
        float4 v = *(float4*)&Es[row * PE + d];
        float4 g = *(const float4*)&gm[d];
        float4 c = *(const float4*)&cosb[r * HD + d];
        float4 s = *(const float4*)&sinb[r * HD + d];
        float x0 = v.x * rs * g.x, x1 = v.y * rs * g.y;
        float x2 = v.z * rs * g.z, x3 = v.w * rs * g.w;
        uint2 o;
        o.x = pack_h2((x0 * c.x - x1 * s.x) * mult, (x1 * c.y + x0 * s.y) * mult);
        o.y = pack_h2((x2 * c.z - x3 * s.z) * mult, (x3 * c.w + x2 * s.w) * mult);
        *(uint2*)&dst[(size_t)r * DM + n0 + d] = o;
    }
}

// ============================================================================
// Fused flash attention — R13 version verbatim (measured 224.5 us).
// fp16 mma + ldmatrix + ex2 softmax, one syncthreads per chunk.
// ============================================================================

#define PQ 136
#define PVT 72
#define FLASH_SMEM (128*PQ*2 + 2*64*PQ*2 + 2*128*PVT*2)

__global__ __launch_bounds__(256, 2) void k_flash()
{
    extern __shared__ char smraw[];
    __half* Qs  = (__half*)smraw;
    __half* KsB = Qs + 128 * PQ;
    __half* VsB = KsB + 2 * 64 * PQ;

    const int tid  = threadIdx.x;
    const int warp = tid >> 5, lane = tid & 31;
    const int l16 = lane & 15;
    const int lh  = (lane >> 4) << 3;
    const int h  = blockIdx.y;
    const int m0 = blockIdx.x * 128;

    auto issue_chunk = [&](int c, int stage) {
        const int s0 = c * 64;
        __half* Kd = KsB + stage * 64 * PQ;
        __half* Vd = VsB + stage * 128 * PVT;
#pragma unroll
        for (int q = 0; q < 4; q++) {
            int idx = tid + q * 256;
            {
                int row = idx >> 4, off = (idx & 15) * 8;
                cp16(Kd + row * PQ + off,
                     g_K + (size_t)(s0 + row) * DM + h * HD + off);
            }
            {
                int row = idx >> 3, off = (idx & 7) * 8;
                cp16(Vd + row * PVT + off,
                     g_Vt + ((size_t)h * HD + row) * S_ALL + s0 + off);
            }
        }
        CP_COMMIT();
    };

#pragma unroll
    for (int q = 0; q < 8; q++) {
        int idx = tid + q * 256;
        int row = idx >> 4, off = (idx & 15) * 8;
        cp16(Qs + row * PQ + off, g_Q + (size_t)(m0 + row) * DM + h * HD + off);
    }
    issue_chunk(0, 0);

    float m_r0 = -1e30f, m_r1 = -1e30f;
    float l_r0 = 0.f,    l_r1 = 0.f;
    float O[16][4];
#pragma unroll
    for (int i = 0; i < 16; i++)
#pragma unroll
        for (int j = 0; j < 4; j++) O[i][j] = 0.f;

    const int rb = warp * 16;
    const int NCH = S_ALL / 64;

    for (int c = 0; c < NCH; c++) {
        const int cur = c & 1;
        CP_WAIT0();
        __syncthreads();
        if (c + 1 < NCH) issue_chunk(c + 1, cur ^ 1);

        const __half* Ks = KsB + cur * 64 * PQ;
        const __half* Vs = VsB + cur * 128 * PVT;

        // ---- S' = (Q*log2e/sqrt(d)) K^T
        float sacc[8][4];
#pragma unroll
        for (int nt = 0; nt < 8; nt++)
#pragma unroll
            for (int r = 0; r < 4; r++) sacc[nt][r] = 0.f;

#pragma unroll
        for (int kk = 0; kk < HD; kk += 16) {
            uint32_t a0, a1, a2, a3;
            uint32_t qa = sptr(&Qs[(rb + l16) * PQ + kk + lh]);
            LDSM_X4(a0, a1, a2, a3, qa);
            uint32_t b[8][2];
#pragma unroll
            for (int nt = 0; nt < 8; nt += 2) {
                uint32_t kd = sptr(&Ks[(nt * 8 + l16) * PQ + kk + lh]);
                LDSM_X4(b[nt][0], b[nt + 1][0], b[nt][1], b[nt + 1][1], kd);
            }
#pragma unroll
            for (int nt = 0; nt < 8; nt++)
                MMA16(sacc[nt][0], sacc[nt][1], sacc[nt][2], sacc[nt][3],
                      a0, a1, a2, a3, b[nt][0], b[nt][1]);
        }

        // ---- online softmax (base-2)
        float cm0 = -1e30f, cm1 = -1e30f;
#pragma unroll
        for (int nt = 0; nt < 8; nt++) {
            cm0 = fmaxf(cm0, fmaxf(sacc[nt][0], sacc[nt][1]));
            cm1 = fmaxf(cm1, fmaxf(sacc[nt][2], sacc[nt][3]));
        }
        cm0 = fmaxf(cm0, __shfl_xor_sync(0xffffffffu, cm0, 1));
        cm0 = fmaxf(cm0, __shfl_xor_sync(0xffffffffu, cm0, 2));
        cm1 = fmaxf(cm1, __shfl_xor_sync(0xffffffffu, cm1, 1));
        cm1 = fmaxf(cm1, __shfl_xor_sync(0xffffffffu, cm1, 2));

        float mn0 = fmaxf(m_r0, cm0), mn1 = fmaxf(m_r1, cm1);
        float al0 = ex2(m_r0 - mn0), al1 = ex2(m_r1 - mn1);
        m_r0 = mn0; m_r1 = mn1;

        uint32_t ph[8][2];
        float cs0 = 0.f, cs1 = 0.f;
#pragma unroll
        for (int nt = 0; nt < 8; nt++) {
            float p0 = ex2(sacc[nt][0] - mn0);
            float p1 = ex2(sacc[nt][1] - mn0);
            float p2 = ex2(sacc[nt][2] - mn1);
            float p3 = ex2(sacc[nt][3] - mn1);
            ph[nt][0] = pack_h2(p0, p1);
            ph[nt][1] = pack_h2(p2, p3);
            cs0 += p0 + p1;
            cs1 += p2 + p3;
        }
        cs0 += __shfl_xor_sync(0xffffffffu, cs0, 1);
        cs0 += __shfl_xor_sync(0xffffffffu, cs0, 2);
        cs1 += __shfl_xor_sync(0xffffffffu, cs1, 1);
        cs1 += __shfl_xor_sync(0xffffffffu, cs1, 2);
        l_r0 = l_r0 * al0 + cs0;
        l_r1 = l_r1 * al1 + cs1;

#pragma unroll
        for (int nt2 = 0; nt2 < 16; nt2++) {
            O[nt2][0] *= al0; O[nt2][1] *= al0;
            O[nt2][2] *= al1; O[nt2][3] *= al1;
        }

        // ---- O += P V
#pragma unroll
        for (int ks = 0; ks < 4; ks++) {
            uint32_t a0 = ph[2 * ks][0];
            uint32_t a1 = ph[2 * ks][1];
            uint32_t a2 = ph[2 * ks + 1][0];
            uint32_t a3 = ph[2 * ks + 1][1];
#pragma unroll
            for (int nt2 = 0; nt2 < 16; nt2 += 2) {
                uint32_t b0, b1, b2, b3;
                uint32_t vd = sptr(&Vs[(nt2 * 8 + l16) * PVT + ks * 16 + lh]);
                LDSM_X4(b0, b1, b2, b3, vd);
                MMA16(O[nt2][0], O[nt2][1], O[nt2][2], O[nt2][3],
                      a0, a1, a2, a3, b0, b2);
                MMA16(O[nt2 + 1][0], O[nt2 + 1][1], O[nt2 + 1][2], O[nt2 + 1][3],
                      a0, a1, a2, a3, b1, b3);
            }
        }
    }

    // ---- epilogue
    const int lr = lane >> 2, lc = lane & 3;
    float i0 = 1.0f / l_r0, i1 = 1.0f / l_r1;
    const int row0 = m0 + rb + lr;
#pragma unroll
    for (int nt2 = 0; nt2 < 16; nt2++) {
        int col = h * HD + nt2 * 8 + 2 * lc;
        *(uint32_t*)&g_O[(size_t)row0 * DM + col] =
            pack_h2(O[nt2][0] * i0, O[nt2][1] * i0);
        *(uint32_t*)&g_O[(size_t)(row0 + 8) * DM + col] =
            pack_h2(O[nt2][2] * i1, O[nt2][3] * i1);
    }
}

// ---- output projections ------------------------------------------------------
__global__ __launch_bounds__(256, 2) void k_outproj(
    const float* __restrict__ b_out, const float* __restrict__ b_ao,
    float* __restrict__ outbuf)
{
    const int n0 = blockIdx.x * 128;
    const int m0 = blockIdx.y * 128;
    const bool is_enc = (m0 < STXT);
    const __half* B = g_Wt + (size_t)(is_enc ? 7 : 6) * DM * DM + (size_t)n0 * DM;
    const float* bias = (is_enc ? b_ao : b_out) + n0;
    float* out = is_enc ? (outbuf + (size_t)SIMG * DM + (size_t)m0 * DM)
                        : (outbuf + (size_t)(m0 - STXT) * DM);

    float acc[4][4][4];
    gemm_core_h(g_O + (size_t)m0 * DM, B, acc);

    const int tid  = threadIdx.x;
    const int warp = tid >> 5, lane = tid & 31;
    const int wm = (warp >> 2) * 64;
    const int wn = (warp & 3)  * 32;
    const int lr = lane >> 2, lc = lane & 3;

#pragma unroll
    for (int mt = 0; mt < 4; mt++) {
        int row = wm + mt * 16 + lr;
#pragma unroll
        for (int nt = 0; nt < 4; nt++) {
            int col = wn + nt * 8 + 2 * lc;
            float b0 = bias[col];
            float b1 = bias[col + 1];
            float2 lo = make_float2(acc[mt][nt][0] + b0, acc[mt][nt][1] + b1);
            float2 hi = make_float2(acc[mt][nt][2] + b0, acc[mt][nt][3] + b1);
            *(float2*)&out[(size_t)row * DM + n0 + col]       = lo;
            *(float2*)&out[(size_t)(row + 8) * DM + n0 + col] = hi;
        }
    }
}

// ============================================================================
extern "C" void kernel_launch(void* const* d_in, const int* in_sizes, int n_in,
                              void* d_out, int out_size)
{
    const float* hid  = (const float*)d_in[0];
    const float* enc  = (const float*)d_in[1];
    const float* cosb = (const float*)d_in[2];
    const float* sinb = (const float*)d_in[3];
    const float* wq   = (const float*)d_in[4];
    const float* wk   = (const float*)d_in[5];
    const float* wv   = (const float*)d_in[6];
    const float* wqa  = (const float*)d_in[7];
    const float* wka  = (const float*)d_in[8];
    const float* wva  = (const float*)d_in[9];
    const float* bqa  = (const float*)d_in[10];
    const float* bka  = (const float*)d_in[11];
    const float* bva  = (const float*)d_in[12];
    const float* nq   = (const float*)d_in[13];
    const float* nk   = (const float*)d_in[14];
    const float* naq  = (const float*)d_in[15];
    const float* nak  = (const float*)d_in[16];
    const float* wout = (const float*)d_in[17];
    const float* bout = (const float*)d_in[18];
    const float* wao  = (const float*)d_in[19];
    const float* bao  = (const float*)d_in[20];
    float* out = (float*)d_out;

    cudaFuncSetAttribute(k_qkv,     cudaFuncAttributeMaxDynamicSharedMemorySize, GEMM_SMEM);
    cudaFuncSetAttribute(k_outproj, cudaFuncAttributeMaxDynamicSharedMemorySize, GEMM_SMEM);
    cudaFuncSetAttribute(k_flash,   cudaFuncAttributeMaxDynamicSharedMemorySize, FLASH_SMEM);

    k_round_act<<<512, 256>>>(hid, enc);
    dim3 tw_grid(DM / 32, DM / 32, 8);
    k_transw<<<tw_grid, 256>>>(wq, wk, wv, wqa, wka, wva, wout, wao);

    dim3 qkv_grid(DM / 128, S_ALL / 128, 3);        // 24 x 18 x 3
    k_qkv<<<qkv_grid, 256, GEMM_SMEM>>>(bqa, bka, bva,
                                        nq, naq, nk, nak, cosb, sinb);

    dim3 fl_grid(S_ALL / 128, NH);                  // 18 x 24
    k_flash<<<fl_grid, 256, FLASH_SMEM>>>();

    dim3 gemm_grid(DM / 128, S_ALL / 128);          // 24 x 18
    k_outproj<<<gemm_grid, 256, GEMM_SMEM>>>(bout, bao, out);
}

// round 16
// speedup vs baseline: 1.0221x; 1.0024x over previous
#include <cuda_runtime.h>
#include <cuda_fp16.h>
#include <math.h>
#include <stdint.h>

#define S_ALL 2304
#define STXT  256
#define SIMG  2048
#define DM    3072
#define NH    24
#define HD    128

// ---------------- scratch (static device globals; no runtime allocation) ----
__device__ __half g_X [S_ALL * DM];                // concat(enc,hid) fp16
__device__ __half g_Q [S_ALL * DM];                // fp16, pre-scaled log2e/sqrt(128)
__device__ __half g_K [S_ALL * DM];                // fp16 natural [s][d]
__device__ __half g_Vt[NH * HD * S_ALL];           // fp16 transposed [h][d][s]
__device__ __half g_O [S_ALL * DM];                // fp16
__device__ __half g_Wt[(size_t)8 * DM * DM];       // fp16 transposed weights [n][k]

__device__ __forceinline__ void cp16(void* dst, const void* src) {
    uint32_t s = (uint32_t)__cvta_generic_to_shared(dst);
    asm volatile("cp.async.cg.shared.global [%0], [%1], 16;" :: "r"(s), "l"(src));
}
#define CP_COMMIT() asm volatile("cp.async.commit_group;")
#define CP_WAIT1()  asm volatile("cp.async.wait_group 1;")
#define CP_WAIT0()  asm volatile("cp.async.wait_group 0;")

#define MMA16(d0,d1,d2,d3,a0,a1,a2,a3,b0,b1)                                  \
    asm("mma.sync.aligned.m16n8k16.row.col.f32.f16.f16.f32 "                  \
        "{%0,%1,%2,%3}, {%4,%5,%6,%7}, {%8,%9}, {%0,%1,%2,%3};"               \
        : "+f"(d0), "+f"(d1), "+f"(d2), "+f"(d3)                              \
        : "r"(a0), "r"(a1), "r"(a2), "r"(a3), "r"(b0), "r"(b1))

#define LDSM_X4(r0,r1,r2,r3,addr)                                             \
    asm volatile("ldmatrix.sync.aligned.m8n8.x4.shared.b16 {%0,%1,%2,%3}, [%4];" \
        : "=r"(r0), "=r"(r1), "=r"(r2), "=r"(r3) : "r"(addr))

__device__ __forceinline__ uint32_t sptr(const void* p) {
    return (uint32_t)__cvta_generic_to_shared(p);
}
__device__ __forceinline__ uint32_t pack_h2(float a, float b) {
    __half2 h = __floats2half2_rn(a, b);
    return *(uint32_t*)&h;
}
__device__ __forceinline__ float ex2(float x) {
    float r;
    asm("ex2.approx.f32 %0, %1;" : "=f"(r) : "f"(x));
    return r;
}

// ============================================================================
// fp16 GEMM core: 128x128 block, 8 warps (2x4), warp tile 64x32, k-chunk 64,
// 3-stage cp.async, ldmatrix frag loads, one syncthreads per chunk,
// unroll-3 main loop (static stage indices).
// ============================================================================

#define PH 72
#define PE 132
#define NSTG 3
#define GEMM_SMEM (NSTG * 2 * 128 * PH * 2)

__device__ __forceinline__ void gemm_core_h(
    const __half* __restrict__ A, const __half* __restrict__ B,
    float acc[4][4][4])
{
    extern __shared__ char dsraw[];
    __half* AsB = (__half*)dsraw;
    __half* BsB = AsB + NSTG * 128 * PH;

    const int tid  = threadIdx.x;
    const int warp = tid >> 5, lane = tid & 31;
    const int wm = (warp >> 2) * 64;
    const int wn = (warp & 3)  * 32;
    const int l16 = lane & 15;
    const int lh  = (lane >> 4) << 3;

#pragma unroll
    for (int mt = 0; mt < 4; mt++)
#pragma unroll
        for (int nt = 0; nt < 4; nt++)
#pragma unroll
            for (int r = 0; r < 4; r++) acc[mt][nt][r] = 0.f;

    const int srow = tid >> 1;
    const int soff = (tid & 1) * 32;

    auto issue = [&](int k0, int stage) {
        const __half* Ag = A + (size_t)srow * DM + k0 + soff;
        __half* Ad = AsB + stage * 128 * PH + srow * PH + soff;
#pragma unroll
        for (int i = 0; i < 4; i++) cp16(Ad + i * 8, Ag + i * 8);
        const __half* Bg = B + (size_t)srow * DM + k0 + soff;
        __half* Bd = BsB + stage * 128 * PH + srow * PH + soff;
#pragma unroll
        for (int i = 0; i < 4; i++) cp16(Bd + i * 8, Bg + i * 8);
        CP_COMMIT();
    };

    const int ntile = DM / 64;   // 48
    issue(0, 0);
    issue(64, 1);

#pragma unroll 3
    for (int t = 0; t < ntile; t++) {
        const int cur = t % NSTG;
        if (t + 1 < ntile) { CP_WAIT1(); } else { CP_WAIT0(); }
        __syncthreads();
        if (t + 2 < ntile) issue((t + 2) * 64, (t + 2) % NSTG);

        const __half* As = AsB + cur * 128 * PH;
        const __half* Bs = BsB + cur * 128 * PH;

#pragma unroll
        for (int kk = 0; kk < 64; kk += 16) {
            uint32_t a[4][4], b[4][2];
#pragma unroll
            for (int mt = 0; mt < 4; mt++) {
                uint32_t ad = sptr(&As[(wm + mt * 16 + l16) * PH + kk + lh]);
                LDSM_X4(a[mt][0], a[mt][1], a[mt][2], a[mt][3], ad);
            }
#pragma unroll
            for (int nt = 0; nt < 4; nt += 2) {
                uint32_t bd = sptr(&Bs[(wn + nt * 8 + l16) * PH + kk + lh]);
                LDSM_X4(b[nt][0], b[nt + 1][0], b[nt][1], b[nt + 1][1], bd);
            }
#pragma unroll
            for (int mt = 0; mt < 4; mt++)
#pragma unroll
                for (int nt = 0; nt < 4; nt++)
                    MMA16(acc[mt][nt][0], acc[mt][nt][1], acc[mt][nt][2], acc[mt][nt][3],
                          a[mt][0], a[mt][1], a[mt][2], a[mt][3],
                          b[nt][0], b[nt][1]);
        }
    }
    __syncthreads();
}

// ---- pre-pass: concat + fp16-convert activations ----------------------------
__global__ __launch_bounds__(256) void k_round_act(
    const float* __restrict__ hid, const float* __restrict__ enc)
{
    const int total = S_ALL * DM / 4;
    for (int i = blockIdx.x * blockDim.x + threadIdx.x; i < total;
         i += gridDim.x * blockDim.x) {
        int r = (i * 4) / DM, c = (i * 4) % DM;
        const float* s = (r < STXT) ? enc + (size_t)r * DM + c
                                    : hid + (size_t)(r - STXT) * DM + c;
        float4 v = *(const float4*)s;
        uint2 o;
        o.x = pack_h2(v.x, v.y);
        o.y = pack_h2(v.z, v.w);
        *(uint2*)&g_X[(size_t)i * 4] = o;
    }
}

// ---- pre-pass: transpose + fp16-convert the 8 weight matrices ---------------
__global__ __launch_bounds__(256) void k_transw(
    const float* __restrict__ w0, const float* __restrict__ w1,
    const float* __restrict__ w2, const float* __restrict__ w3,
    const float* __restrict__ w4, const float* __restrict__ w5,
    const float* __restrict__ w6, const float* __restrict__ w7)
{
    __shared__ float t[32][33];
    const float* W =
        (blockIdx.z == 0) ? w0 : (blockIdx.z == 1) ? w1 : (blockIdx.z == 2) ? w2 :
        (blockIdx.z == 3) ? w3 : (blockIdx.z == 4) ? w4 : (blockIdx.z == 5) ? w5 :
        (blockIdx.z == 6) ? w6 : w7;
    __half* Wt = g_Wt + (size_t)blockIdx.z * DM * DM;

    const int bx = blockIdx.x * 32;
    const int by = blockIdx.y * 32;
    const int tx = threadIdx.x & 31, ty = threadIdx.x >> 5;

#pragma unroll
    for (int j = ty; j < 32; j += 8)
        t[j][tx] = W[(size_t)(by + j) * DM + bx + tx];
    __syncthreads();
#pragma unroll
    for (int j = ty; j < 32; j += 8)
        Wt[(size_t)(bx + j) * DM + by + tx] = __float2half_rn(t[tx][j]);
}

// ---- QKV projection + fused RMSNorm/RoPE epilogue (fp16 outputs) ------------
__global__ __launch_bounds__(256, 2) void k_qkv(
    const float* __restrict__ bqa, const float* __restrict__ bka,
    const float* __restrict__ bva,
    const float* __restrict__ nq,  const float* __restrict__ naq,
    const float* __restrict__ nk,  const float* __restrict__ nak,
    const float* __restrict__ cosb, const float* __restrict__ sinb)
{
    extern __shared__ char dsraw[];
    const int which = blockIdx.z;
    const float* badd = (which == 0) ? bqa : (which == 1) ? bka : bva;

    const int n0 = blockIdx.x * 128;
    const int m0 = blockIdx.y * 128;
    const bool is_enc = (m0 < STXT);
    const int slot = which + (is_enc ? 3 : 0);

    const __half* A = g_X + (size_t)m0 * DM;
    const __half* B = g_Wt + (size_t)slot * DM * DM + (size_t)n0 * DM;

    float acc[4][4][4];
    gemm_core_h(A, B, acc);

    const int tid  = threadIdx.x;
    const int warp = tid >> 5, lane = tid & 31;
    const int wm = (warp >> 2) * 64;
    const int wn = (warp & 3)  * 32;
    const int lr = lane >> 2, lc = lane & 3;

    float* Es = (float*)dsraw;  // 128 x PE
#pragma unroll
    for (int mt = 0; mt < 4; mt++) {
        int row = wm + mt * 16 + lr;
#pragma unroll
        for (int nt = 0; nt < 4; nt++) {
            int col = wn + nt * 8 + 2 * lc;
            float b0 = is_enc ? badd[n0 + col]     : 0.f;
            float b1 = is_enc ? badd[n0 + col + 1] : 0.f;
            float2 lo = make_float2(acc[mt][nt][0] + b0, acc[mt][nt][1] + b1);
            float2 hi = make_float2(acc[mt][nt][2] + b0, acc[mt][nt][3] + b1);
            *(float2*)&Es[row * PE + col]       = lo;
            *(float2*)&Es[(row + 8) * PE + col] = hi;
        }
    }
    __syncthreads();

    if (which == 2) {
        const int h = blockIdx.x;
        const int d  = tid >> 1;
        const int ms = (tid & 1) * 64;
        __half* dstv = g_Vt + ((size_t)h * HD + d) * S_ALL + m0 + ms;
#pragma unroll
        for (int j = 0; j < 64; j += 2) {
            float v0 = Es[(ms + j)     * PE + d];
            float v1 = Es[(ms + j + 1) * PE + d];
            *(uint32_t*)&dstv[j] = pack_h2(v0, v1);
        }
        return;
    }

    const float* gm = is_enc ? (which == 0 ? naq : nak)
                             : (which == 0 ? nq  : nk);
    __half* dst = (which == 0) ? g_Q : g_K;
    const float mult = (which == 0)
        ? 0.088388347648318447f * 1.4426950408889634f : 1.0f;

    const int row   = tid >> 1;
    const int cbase = (tid & 1) * 64;
    const int r     = m0 + row;

    float ss = 0.f;
#pragma unroll
    for (int i = 0; i < 64; i += 4) {
        float4 v = *(float4*)&Es[row * PE + cbase + i];
        ss += v.x * v.x + v.y * v.y + v.z * v.z + v.w * v.w;
    }
    ss += __shfl_xor_sync(0xffffffffu, ss, 1);
    float rs = rsqrtf(ss * (1.0f / HD) + 1e-6f);

#pragma unroll
    for (int i = 0; i < 64; i += 4) {
        int d = cbase + i;
        float4 v = *(float4*)&Es[row * PE + d];
        float4 g = *(const float4*)&gm[d];
        float4 c = *(const float4*)&cosb[r * HD + d];
        float4 s = *(const float4*)&sinb[r * HD + d];
        float x0 = v.x * rs * g.x, x1 = v.y * rs * g.y;
        float x2 = v.z * rs * g.z, x3 = v.w * rs * g.w;
        uint2 o;
        o.x = pack_h2((x0 * c.x - x1 * s.x) * mult, (x1 * c.y + x0 * s.y) * mult);
        o.y = pack_h2((x2 * c.z - x3 * s.z) * mult, (x3 * c.w + x2 * s.w) * mult);
        *(uint2*)&dst[(size_t)r * DM + n0 + d] = o;
    }
}

// ============================================================================
// Fused flash attention, fp16 mma + ldmatrix + ex2 softmax.
// WARP-UNIFORM running max: O-rescale (64 FMUL) runs only when the max
// actually increases (uniform branch, ~90% of chunks skip it).
// ============================================================================

#define PQ 136
#define PVT 72
#define FLASH_SMEM (128*PQ*2 + 2*64*PQ*2 + 2*128*PVT*2)

__global__ __launch_bounds__(256, 2) void k_flash()
{
    extern __shared__ char smraw[];
    __half* Qs  = (__half*)smraw;
    __half* KsB = Qs + 128 * PQ;
    __half* VsB = KsB + 2 * 64 * PQ;

    const int tid  = threadIdx.x;
    const int warp = tid >> 5, lane = tid & 31;
    const int l16 = lane & 15;
    const int lh  = (lane >> 4) << 3;
    const int h  = blockIdx.y;
    const int m0 = blockIdx.x * 128;

    auto issue_chunk = [&](int c, int stage) {
        const int s0 = c * 64;
        __half* Kd = KsB + stage * 64 * PQ;
        __half* Vd = VsB + stage * 128 * PVT;
#pragma unroll
        for (int q = 0; q < 4; q++) {
            int idx = tid + q * 256;
            {
                int row = idx >> 4, off = (idx & 15) * 8;
                cp16(Kd + row * PQ + off,
                     g_K + (size_t)(s0 + row) * DM + h * HD + off);
            }
            {
                int row = idx >> 3, off = (idx & 7) * 8;
                cp16(Vd + row * PVT + off,
                     g_Vt + ((size_t)h * HD + row) * S_ALL + s0 + off);
            }
        }
        CP_COMMIT();
    };

#pragma unroll
    for (int q = 0; q < 8; q++) {
        int idx = tid + q * 256;
        int row = idx >> 4, off = (idx & 15) * 8;
        cp16(Qs + row * PQ + off, g_Q + (size_t)(m0 + row) * DM + h * HD + off);
    }
    issue_chunk(0, 0);

    float m_r  = -1e30f;                 // warp-uniform running max
    float l_r0 = 0.f, l_r1 = 0.f;        // per-row sums (rows lr, lr+8)
    float O[16][4];
#pragma unroll
    for (int i = 0; i < 16; i++)
#pragma unroll
        for (int j = 0; j < 4; j++) O[i][j] = 0.f;

    const int rb = warp * 16;
    const int NCH = S_ALL / 64;

    for (int c = 0; c < NCH; c++) {
        const int cur = c & 1;
        CP_WAIT0();
        __syncthreads();
        if (c + 1 < NCH) issue_chunk(c + 1, cur ^ 1);

        const __half* Ks = KsB + cur * 64 * PQ;
        const __half* Vs = VsB + cur * 128 * PVT;

        // ---- S' = (Q*log2e/sqrt(d)) K^T
        float sacc[8][4];
#pragma unroll
        for (int nt = 0; nt < 8; nt++)
#pragma unroll
            for (int r = 0; r < 4; r++) sacc[nt][r] = 0.f;

#pragma unroll
        for (int kk = 0; kk < HD; kk += 16) {
            uint32_t a0, a1, a2, a3;
            uint32_t qa = sptr(&Qs[(rb + l16) * PQ + kk + lh]);
            LDSM_X4(a0, a1, a2, a3, qa);
            uint32_t b[8][2];
#pragma unroll
            for (int nt = 0; nt < 8; nt += 2) {
                uint32_t kd = sptr(&Ks[(nt * 8 + l16) * PQ + kk + lh]);
                LDSM_X4(b[nt][0], b[nt + 1][0], b[nt][1], b[nt + 1][1], kd);
            }
#pragma unroll
            for (int nt = 0; nt < 8; nt++)
                MMA16(sacc[nt][0], sacc[nt][1], sacc[nt][2], sacc[nt][3],
                      a0, a1, a2, a3, b[nt][0], b[nt][1]);
        }

        // ---- warp-uniform max over this chunk
        float cm = -1e30f;
#pragma unroll
        for (int nt = 0; nt < 8; nt++) {
            cm = fmaxf(cm, fmaxf(sacc[nt][0], sacc[nt][1]));
            cm = fmaxf(cm, fmaxf(sacc[nt][2], sacc[nt][3]));
        }
        cm = fmaxf(cm, __shfl_xor_sync(0xffffffffu, cm, 16));
        cm = fmaxf(cm, __shfl_xor_sync(0xffffffffu, cm, 8));
        cm = fmaxf(cm, __shfl_xor_sync(0xffffffffu, cm, 4));
        cm = fmaxf(cm, __shfl_xor_sync(0xffffffffu, cm, 2));
        cm = fmaxf(cm, __shfl_xor_sync(0xffffffffu, cm, 1));

        // uniform branch: rescale only when the max increases
        if (cm > m_r) {
            float al = ex2(m_r - cm);
            m_r = cm;
            l_r0 *= al; l_r1 *= al;
#pragma unroll
            for (int nt2 = 0; nt2 < 16; nt2++) {
                O[nt2][0] *= al; O[nt2][1] *= al;
                O[nt2][2] *= al; O[nt2][3] *= al;
            }
        }

        uint32_t ph[8][2];
        float cs0 = 0.f, cs1 = 0.f;
#pragma unroll
        for (int nt = 0; nt < 8; nt++) {
            float p0 = ex2(sacc[nt][0] - m_r);
            float p1 = ex2(sacc[nt][1] - m_r);
            float p2 = ex2(sacc[nt][2] - m_r);
            float p3 = ex2(sacc[nt][3] - m_r);
            ph[nt][0] = pack_h2(p0, p1);
            ph[nt][1] = pack_h2(p2, p3);
            cs0 += p0 + p1;
            cs1 += p2 + p3;
        }
        cs0 += __shfl_xor_sync(0xffffffffu, cs0, 1);
        cs0 += __shfl_xor_sync(0xffffffffu, cs0, 2);
        cs1 += __shfl_xor_sync(0xffffffffu, cs1, 1);
        cs1 += __shfl_xor_sync(0xffffffffu, cs1, 2);
        l_r0 += cs0;
        l_r1 += cs1;

        // ---- O += P V
#pragma unroll
        for (int ks = 0; ks < 4; ks++) {
            uint32_t a0 = ph[2 * ks][0];
            uint32_t a1 = ph[2 * ks][1];
            uint32_t a2 = ph[2 * ks + 1][0];
            uint32_t a3 = ph[2 * ks + 1][1];
#pragma unroll
            for (int nt2 = 0; nt2 < 16; nt2 += 2) {
                uint32_t b0, b1, b2, b3;
                uint32_t vd = sptr(&Vs[(nt2 * 8 + l16) * PVT + ks * 16 + lh]);
                LDSM_X4(b0, b1, b2, b3, vd);
                MMA16(O[nt2][0], O[nt2][1], O[nt2][2], O[nt2][3],
                      a0, a1, a2, a3, b0, b2);
                MMA16(O[nt2 + 1][0], O[nt2 + 1][1], O[nt2 + 1][2], O[nt2 + 1][3],
                      a0, a1, a2, a3, b1, b3);
            }
        }
    }

    // ---- epilogue
    const int lr = lane >> 2, lc = lane & 3;
    float i0 = 1.0f / l_r0, i1 = 1.0f / l_r1;
    const int row0 = m0 + rb + lr;
#pragma unroll
    for (int nt2 = 0; nt2 < 16; nt2++) {
        int col = h * HD + nt2 * 8 + 2 * lc;
        *(uint32_t*)&g_O[(size_t)row0 * DM + col] =
            pack_h2(O[nt2][0] * i0, O[nt2][1] * i0);
        *(uint32_t*)&g_O[(size_t)(row0 + 8) * DM + col] =
            pack_h2(O[nt2][2] * i1, O[nt2][3] * i1);
    }
}

// ---- output projections ------------------------------------------------------
__global__ __launch_bounds__(256, 2) void k_outproj(
    const float* __restrict__ b_out, const float* __restrict__ b_ao,
    float* __restrict__ outbuf)
{
    const int n0 = blockIdx.x * 128;
    const int m0 = blockIdx.y * 128;
    const bool is_enc = (m0 < STXT);
    const __half* B = g_Wt + (size_t)(is_enc ? 7 : 6) * DM * DM + (size_t)n0 * DM;
    const float* bias = (is_enc ? b_ao : b_out) + n0;
    float* out = is_enc ? (outbuf + (size_t)SIMG * DM + (size_t)m0 * DM)
                        : (outbuf + (size_t)(m0 - STXT) * DM);

    float acc[4][4][4];
    gemm_core_h(g_O + (size_t)m0 * DM, B, acc);

    const int tid  = threadIdx.x;
    const int warp = tid >> 5, lane = tid & 31;
    const int wm = (warp >> 2) * 64;
    const int wn = (warp & 3)  * 32;
    const int lr = lane >> 2, lc = lane & 3;

#pragma unroll
    for (int mt = 0; mt < 4; mt++) {
        int row = wm + mt * 16 + lr;
#pragma unroll
        for (int nt = 0; nt < 4; nt++) {
            int col = wn + nt * 8 + 2 * lc;
            float b0 = bias[col];
            float b1 = bias[col + 1];
            float2 lo = make_float2(acc[mt][nt][0] + b0, acc[mt][nt][1] + b1);
            float2 hi = make_float2(acc[mt][nt][2] + b0, acc[mt][nt][3] + b1);
            *(float2*)&out[(size_t)row * DM + n0 + col]       = lo;
            *(float2*)&out[(size_t)(row + 8) * DM + n0 + col] = hi;
        }
    }
}

// ============================================================================
extern "C" void kernel_launch(void* const* d_in, const int* in_sizes, int n_in,
                              void* d_out, int out_size)
{
    const float* hid  = (const float*)d_in[0];
    const float* enc  = (const float*)d_in[1];
    const float* cosb = (const float*)d_in[2];
    const float* sinb = (const float*)d_in[3];
    const float* wq   = (const float*)d_in[4];
    const float* wk   = (const float*)d_in[5];
    const float* wv   = (const float*)d_in[6];
    const float* wqa  = (const float*)d_in[7];
    const float* wka  = (const float*)d_in[8];
    const float* wva  = (const float*)d_in[9];
    const float* bqa  = (const float*)d_in[10];
    const float* bka  = (const float*)d_in[11];
    const float* bva  = (const float*)d_in[12];
    const float* nq   = (const float*)d_in[13];
    const float* nk   = (const float*)d_in[14];
    const float* naq  = (const float*)d_in[15];
    const float* nak  = (const float*)d_in[16];
    const float* wout = (const float*)d_in[17];
    const float* bout = (const float*)d_in[18];
    const float* wao  = (const float*)d_in[19];
    const float* bao  = (const float*)d_in[20];
    float* out = (float*)d_out;

    cudaFuncSetAttribute(k_qkv,     cudaFuncAttributeMaxDynamicSharedMemorySize, GEMM_SMEM);
    cudaFuncSetAttribute(k_outproj, cudaFuncAttributeMaxDynamicSharedMemorySize, GEMM_SMEM);
    cudaFuncSetAttribute(k_flash,   cudaFuncAttributeMaxDynamicSharedMemorySize, FLASH_SMEM);

    k_round_act<<<512, 256>>>(hid, enc);
    dim3 tw_grid(DM / 32, DM / 32, 8);
    k_transw<<<tw_grid, 256>>>(wq, wk, wv, wqa, wka, wva, wout, wao);

    dim3 qkv_grid(DM / 128, S_ALL / 128, 3);        // 24 x 18 x 3
    k_qkv<<<qkv_grid, 256, GEMM_SMEM>>>(bqa, bka, bva,
                                        nq, naq, nk, nak, cosb, sinb);

    dim3 fl_grid(S_ALL / 128, NH);                  // 18 x 24
    k_flash<<<fl_grid, 256, FLASH_SMEM>>>();

    dim3 gemm_grid(DM / 128, S_ALL / 128);          // 24 x 18
    k_outproj<<<gemm_grid, 256, GEMM_SMEM>>>(bout, bao, out);
}

// round 17
// speedup vs baseline: 1.0607x; 1.0378x over previous
#include <cuda_runtime.h>
#include <cuda_fp16.h>
#include <math.h>
#include <stdint.h>

#define S_ALL 2304
#define STXT  256
#define SIMG  2048
#define DM    3072
#define NH    24
#define HD    128

// ---------------- scratch (static device globals; no runtime allocation) ----
__device__ __half g_X [S_ALL * DM];                // concat(enc,hid) fp16
__device__ __half g_Q [S_ALL * DM];                // fp16, pre-scaled log2e/sqrt(128)
__device__ __half g_K [S_ALL * DM];                // fp16 natural [s][d]
__device__ __half g_Vt[NH * HD * S_ALL];           // fp16 transposed [h][d][s]
__device__ __half g_O [S_ALL * DM];                // fp16
__device__ __half g_Wt[(size_t)8 * DM * DM];       // fp16 transposed weights [n][k]

__device__ __forceinline__ void cp16(void* dst, const void* src) {
    uint32_t s = (uint32_t)__cvta_generic_to_shared(dst);
    asm volatile("cp.async.cg.shared.global [%0], [%1], 16;" :: "r"(s), "l"(src));
}
#define CP_COMMIT() asm volatile("cp.async.commit_group;")
#define CP_WAIT1()  asm volatile("cp.async.wait_group 1;")
#define CP_WAIT0()  asm volatile("cp.async.wait_group 0;")

#define MMA16(d0,d1,d2,d3,a0,a1,a2,a3,b0,b1)                                  \
    asm("mma.sync.aligned.m16n8k16.row.col.f32.f16.f16.f32 "                  \
        "{%0,%1,%2,%3}, {%4,%5,%6,%7}, {%8,%9}, {%0,%1,%2,%3};"               \
        : "+f"(d0), "+f"(d1), "+f"(d2), "+f"(d3)                              \
        : "r"(a0), "r"(a1), "r"(a2), "r"(a3), "r"(b0), "r"(b1))

#define LDSM_X4(r0,r1,r2,r3,addr)                                             \
    asm volatile("ldmatrix.sync.aligned.m8n8.x4.shared.b16 {%0,%1,%2,%3}, [%4];" \
        : "=r"(r0), "=r"(r1), "=r"(r2), "=r"(r3) : "r"(addr))

__device__ __forceinline__ uint32_t sptr(const void* p) {
    return (uint32_t)__cvta_generic_to_shared(p);
}
__device__ __forceinline__ uint32_t pack_h2(float a, float b) {
    __half2 h = __floats2half2_rn(a, b);
    return *(uint32_t*)&h;
}
__device__ __forceinline__ float ex2(float x) {
    float r;
    asm("ex2.approx.f32 %0, %1;" : "=f"(r) : "f"(x));
    return r;
}

// ============================================================================
// fp16 GEMM core: 128x128 block, 8 warps (2x4), warp tile 64x32, k-chunk 64,
// 3-stage cp.async, ldmatrix frag loads, one syncthreads per chunk,
// unroll-3 main loop. Prefetch issued AFTER the first k16 step so LSU work
// interleaves with tensor work.
// ============================================================================

#define PH 72
#define PE 132
#define NSTG 3
#define GEMM_SMEM (NSTG * 2 * 128 * PH * 2)

__device__ __forceinline__ void gemm_core_h(
    const __half* __restrict__ A, const __half* __restrict__ B,
    float acc[4][4][4])
{
    extern __shared__ char dsraw[];
    __half* AsB = (__half*)dsraw;
    __half* BsB = AsB + NSTG * 128 * PH;

    const int tid  = threadIdx.x;
    const int warp = tid >> 5, lane = tid & 31;
    const int wm = (warp >> 2) * 64;
    const int wn = (warp & 3)  * 32;
    const int l16 = lane & 15;
    const int lh  = (lane >> 4) << 3;

#pragma unroll
    for (int mt = 0; mt < 4; mt++)
#pragma unroll
        for (int nt = 0; nt < 4; nt++)
#pragma unroll
            for (int r = 0; r < 4; r++) acc[mt][nt][r] = 0.f;

    const int srow = tid >> 1;
    const int soff = (tid & 1) * 32;

    auto issue = [&](int k0, int stage) {
        const __half* Ag = A + (size_t)srow * DM + k0 + soff;
        __half* Ad = AsB + stage * 128 * PH + srow * PH + soff;
#pragma unroll
        for (int i = 0; i < 4; i++) cp16(Ad + i * 8, Ag + i * 8);
        const __half* Bg = B + (size_t)srow * DM + k0 + soff;
        __half* Bd = BsB + stage * 128 * PH + srow * PH + soff;
#pragma unroll
        for (int i = 0; i < 4; i++) cp16(Bd + i * 8, Bg + i * 8);
        CP_COMMIT();
    };

    // one k16 compute step
    auto step = [&](const __half* As, const __half* Bs, int kk) {
        uint32_t a[4][4], b[4][2];
#pragma unroll
        for (int mt = 0; mt < 4; mt++) {
            uint32_t ad = sptr(&As[(wm + mt * 16 + l16) * PH + kk + lh]);
            LDSM_X4(a[mt][0], a[mt][1], a[mt][2], a[mt][3], ad);
        }
#pragma unroll
        for (int nt = 0; nt < 4; nt += 2) {
            uint32_t bd = sptr(&Bs[(wn + nt * 8 + l16) * PH + kk + lh]);
            LDSM_X4(b[nt][0], b[nt + 1][0], b[nt][1], b[nt + 1][1], bd);
        }
#pragma unroll
        for (int mt = 0; mt < 4; mt++)
#pragma unroll
            for (int nt = 0; nt < 4; nt++)
                MMA16(acc[mt][nt][0], acc[mt][nt][1], acc[mt][nt][2], acc[mt][nt][3],
                      a[mt][0], a[mt][1], a[mt][2], a[mt][3],
                      b[nt][0], b[nt][1]);
    };

    const int ntile = DM / 64;   // 48
    issue(0, 0);
    issue(64, 1);

#pragma unroll 3
    for (int t = 0; t < ntile; t++) {
        const int cur = t % NSTG;
        if (t + 1 < ntile) { CP_WAIT1(); } else { CP_WAIT0(); }
        __syncthreads();

        const __half* As = AsB + cur * 128 * PH;
        const __half* Bs = BsB + cur * 128 * PH;

        step(As, Bs, 0);
        if (t + 2 < ntile) issue((t + 2) * 64, (t + 2) % NSTG);
        step(As, Bs, 16);
        step(As, Bs, 32);
        step(As, Bs, 48);
    }
    __syncthreads();
}

// ---- pre-pass: concat + fp16-convert activations ----------------------------
__global__ __launch_bounds__(256) void k_round_act(
    const float* __restrict__ hid, const float* __restrict__ enc)
{
    const int total = S_ALL * DM / 4;
    for (int i = blockIdx.x * blockDim.x + threadIdx.x; i < total;
         i += gridDim.x * blockDim.x) {
        int r = (i * 4) / DM, c = (i * 4) % DM;
        const float* s = (r < STXT) ? enc + (size_t)r * DM + c
                                    : hid + (size_t)(r - STXT) * DM + c;
        float4 v = *(const float4*)s;
        uint2 o;
        o.x = pack_h2(v.x, v.y);
        o.y = pack_h2(v.z, v.w);
        *(uint2*)&g_X[(size_t)i * 4] = o;
    }
}

// ---- pre-pass: transpose + fp16-convert the 8 weight matrices ---------------
__global__ __launch_bounds__(256) void k_transw(
    const float* __restrict__ w0, const float* __restrict__ w1,
    const float* __restrict__ w2, const float* __restrict__ w3,
    const float* __restrict__ w4, const float* __restrict__ w5,
    const float* __restrict__ w6, const float* __restrict__ w7)
{
    __shared__ float t[32][33];
    const float* W =
        (blockIdx.z == 0) ? w0 : (blockIdx.z == 1) ? w1 : (blockIdx.z == 2) ? w2 :
        (blockIdx.z == 3) ? w3 : (blockIdx.z == 4) ? w4 : (blockIdx.z == 5) ? w5 :
        (blockIdx.z == 6) ? w6 : w7;
    __half* Wt = g_Wt + (size_t)blockIdx.z * DM * DM;

    const int bx = blockIdx.x * 32;
    const int by = blockIdx.y * 32;
    const int tx = threadIdx.x & 31, ty = threadIdx.x >> 5;

#pragma unroll
    for (int j = ty; j < 32; j += 8)
        t[j][tx] = W[(size_t)(by + j) * DM + bx + tx];
    __syncthreads();
#pragma unroll
    for (int j = ty; j < 32; j += 8)
        Wt[(size_t)(bx + j) * DM + by + tx] = __float2half_rn(t[tx][j]);
}

// ---- QKV projection + fused RMSNorm/RoPE epilogue (fp16 outputs) ------------
__global__ __launch_bounds__(256, 2) void k_qkv(
    const float* __restrict__ bqa, const float* __restrict__ bka,
    const float* __restrict__ bva,
    const float* __restrict__ nq,  const float* __restrict__ naq,
    const float* __restrict__ nk,  const float* __restrict__ nak,
    const float* __restrict__ cosb, const float* __restrict__ sinb)
{
    extern __shared__ char dsraw[];
    const int which = blockIdx.z;
    const float* badd = (which == 0) ? bqa : (which == 1) ? bka : bva;

    const int n0 = blockIdx.x * 128;
    const int m0 = blockIdx.y * 128;
    const bool is_enc = (m0 < STXT);
    const int slot = which + (is_enc ? 3 : 0);

    const __half* A = g_X + (size_t)m0 * DM;
    const __half* B = g_Wt + (size_t)slot * DM * DM + (size_t)n0 * DM;

    float acc[4][4][4];
    gemm_core_h(A, B, acc);

    const int tid  = threadIdx.x;
    const int warp = tid >> 5, lane = tid & 31;
    const int wm = (warp >> 2) * 64;
    const int wn = (warp & 3)  * 32;
    const int lr = lane >> 2, lc = lane & 3;

    float* Es = (float*)dsraw;  // 128 x PE
#pragma unroll
    for (int mt = 0; mt < 4; mt++) {
        int row = wm + mt * 16 + lr;
#pragma unroll
        for (int nt = 0; nt < 4; nt++) {
            int col = wn + nt * 8 + 2 * lc;
            float b0 = is_enc ? badd[n0 + col]     : 0.f;
            float b1 = is_enc ? badd[n0 + col + 1] : 0.f;
            float2 lo = make_float2(acc[mt][nt][0] + b0, acc[mt][nt][1] + b1);
            float2 hi = make_float2(acc[mt][nt][2] + b0, acc[mt][nt][3] + b1);
            *(float2*)&Es[row * PE + col]       = lo;
            *(float2*)&Es[(row + 8) * PE + col] = hi;
        }
    }
    __syncthreads();

    if (which == 2) {
        const int h = blockIdx.x;
        const int d  = tid >> 1;
        const int ms = (tid & 1) * 64;
        __half* dstv = g_Vt + ((size_t)h * HD + d) * S_ALL + m0 + ms;
#pragma unroll
        for (int j = 0; j < 64; j += 2) {
            float v0 = Es[(ms + j)     * PE + d];
            float v1 = Es[(ms + j + 1) * PE + d];
            *(uint32_t*)&dstv[j] = pack_h2(v0, v1);
        }
        return;
    }

    const float* gm = is_enc ? (which == 0 ? naq : nak)
                             : (which == 0 ? nq  : nk);
    __half* dst = (which == 0) ? g_Q : g_K;
    const float mult = (which == 0)
        ? 0.088388347648318447f * 1.4426950408889634f : 1.0f;

    const int row   = tid >> 1;
    const int cbase = (tid & 1) * 64;
    const int r     = m0 + row;

    float ss = 0.f;
#pragma unroll
    for (int i = 0; i < 64; i += 4) {
        float4 v = *(float4*)&Es[row * PE + cbase + i];
        ss += v.x * v.x + v.y * v.y + v.z * v.z + v.w * v.w;
    }
    ss += __shfl_xor_sync(0xffffffffu, ss, 1);
    float rs = rsqrtf(ss * (1.0f / HD) + 1e-6f);

#pragma unroll
    for (int i = 0; i < 64; i += 4) {
        int d = cbase + i;
        float4 v = *(float4*)&Es[row * PE + d];
        float4 g = *(const float4*)&gm[d];
        float4 c = *(const float4*)&cosb[r * HD + d];
        float4 s = *(const float4*)&sinb[r * HD + d];
        float x0 = v.x * rs * g.x, x1 = v.y * rs * g.y;
        float x2 = v.z * rs * g.z, x3 = v.w * rs * g.w;
        uint2 o;
        o.x = pack_h2((x0 * c.x - x1 * s.x) * mult, (x1 * c.y + x0 * s.y) * mult);
        o.y = pack_h2((x2 * c.z - x3 * s.z) * mult, (x3 * c.w + x2 * s.w) * mult);
        *(uint2*)&dst[(size_t)r * DM + n0 + d] = o;
    }
}

// ============================================================================
// Fused flash attention, fp16 mma + ldmatrix + ex2 softmax.
// l-sum computed by the tensor pipe via a constant-ones B fragment (no smem,
// no shuffles). Hoisted incremental addressing in the K/V loader.
// ============================================================================

#define PQ 136
#define PVT 72
#define FLASH_SMEM (128*PQ*2 + 2*64*PQ*2 + 2*128*PVT*2)
#define H2_ONE 0x3C003C00u

__global__ __launch_bounds__(256, 2) void k_flash()
{
    extern __shared__ char smraw[];
    __half* Qs  = (__half*)smraw;
    __half* KsB = Qs + 128 * PQ;
    __half* VsB = KsB + 2 * 64 * PQ;

    const int tid  = threadIdx.x;
    const int warp = tid >> 5, lane = tid & 31;
    const int l16 = lane & 15;
    const int lh  = (lane >> 4) << 3;
    const int h  = blockIdx.y;
    const int m0 = blockIdx.x * 128;

    // hoisted per-thread loader geometry (chunk-invariant)
    const int krow = tid >> 4, koff = (tid & 15) * 8;   // K: 4 q-steps of +16 rows
    const int vrow = tid >> 3, voff = (tid & 7) * 8;    // V: 4 q-steps of +32 rows
    const __half* gkp = g_K  + (size_t)krow * DM + h * HD + koff;
    const __half* gvp = g_Vt + ((size_t)h * HD + vrow) * S_ALL + voff;
    __half* kd0 = KsB + krow * PQ + koff;
    __half* vd0 = VsB + vrow * PVT + voff;

    auto issue_chunk = [&](int c, int stage) {
        const __half* gk = gkp + (size_t)(c * 64) * DM;
        const __half* gv = gvp + c * 64;
        __half* Kd = kd0 + stage * 64 * PQ;
        __half* Vd = vd0 + stage * 128 * PVT;
#pragma unroll
        for (int q = 0; q < 4; q++) {
            cp16(Kd + q * 16 * PQ,  gk + (size_t)(q * 16) * DM);
            cp16(Vd + q * 32 * PVT, gv + (size_t)(q * 32) * S_ALL);
        }
        CP_COMMIT();
    };

#pragma unroll
    for (int q = 0; q < 8; q++) {
        int idx = tid + q * 256;
        int row = idx >> 4, off = (idx & 15) * 8;
        cp16(Qs + row * PQ + off, g_Q + (size_t)(m0 + row) * DM + h * HD + off);
    }
    issue_chunk(0, 0);

    float m_r = -1e30f;                  // warp-uniform running max
    float lacc[4] = {0.f, 0.f, 0.f, 0.f};// l sums via ones-mma (rows lr, lr+8)
    float O[16][4];
#pragma unroll
    for (int i = 0; i < 16; i++)
#pragma unroll
        for (int j = 0; j < 4; j++) O[i][j] = 0.f;

    const int rb = warp * 16;
    const int NCH = S_ALL / 64;

    for (int c = 0; c < NCH; c++) {
        const int cur = c & 1;
        CP_WAIT0();
        __syncthreads();
        if (c + 1 < NCH) issue_chunk(c + 1, cur ^ 1);

        const __half* Ks = KsB + cur * 64 * PQ;
        const __half* Vs = VsB + cur * 128 * PVT;

        // ---- S' = (Q*log2e/sqrt(d)) K^T
        float sacc[8][4];
#pragma unroll
        for (int nt = 0; nt < 8; nt++)
#pragma unroll
            for (int r = 0; r < 4; r++) sacc[nt][r] = 0.f;

#pragma unroll
        for (int kk = 0; kk < HD; kk += 16) {
            uint32_t a0, a1, a2, a3;
            uint32_t qa = sptr(&Qs[(rb + l16) * PQ + kk + lh]);
            LDSM_X4(a0, a1, a2, a3, qa);
            uint32_t b[8][2];
#pragma unroll
            for (int nt = 0; nt < 8; nt += 2) {
                uint32_t kd = sptr(&Ks[(nt * 8 + l16) * PQ + kk + lh]);
                LDSM_X4(b[nt][0], b[nt + 1][0], b[nt][1], b[nt + 1][1], kd);
            }
#pragma unroll
            for (int nt = 0; nt < 8; nt++)
                MMA16(sacc[nt][0], sacc[nt][1], sacc[nt][2], sacc[nt][3],
                      a0, a1, a2, a3, b[nt][0], b[nt][1]);
        }

        // ---- warp-uniform max over this chunk
        float cm = -1e30f;
#pragma unroll
        for (int nt = 0; nt < 8; nt++) {
            cm = fmaxf(cm, fmaxf(sacc[nt][0], sacc[nt][1]));
            cm = fmaxf(cm, fmaxf(sacc[nt][2], sacc[nt][3]));
        }
        cm = fmaxf(cm, __shfl_xor_sync(0xffffffffu, cm, 16));
        cm = fmaxf(cm, __shfl_xor_sync(0xffffffffu, cm, 8));
        cm = fmaxf(cm, __shfl_xor_sync(0xffffffffu, cm, 4));
        cm = fmaxf(cm, __shfl_xor_sync(0xffffffffu, cm, 2));
        cm = fmaxf(cm, __shfl_xor_sync(0xffffffffu, cm, 1));

        if (cm > m_r) {                  // uniform branch
            float al = ex2(m_r - cm);
            m_r = cm;
            lacc[0] *= al; lacc[1] *= al; lacc[2] *= al; lacc[3] *= al;
#pragma unroll
            for (int nt2 = 0; nt2 < 16; nt2++) {
                O[nt2][0] *= al; O[nt2][1] *= al;
                O[nt2][2] *= al; O[nt2][3] *= al;
            }
        }

        uint32_t ph[8][2];
#pragma unroll
        for (int nt = 0; nt < 8; nt++) {
            float p0 = ex2(sacc[nt][0] - m_r);
            float p1 = ex2(sacc[nt][1] - m_r);
            float p2 = ex2(sacc[nt][2] - m_r);
            float p3 = ex2(sacc[nt][3] - m_r);
            ph[nt][0] = pack_h2(p0, p1);
            ph[nt][1] = pack_h2(p2, p3);
        }

        // ---- O += P V  (+ l += P x ones, on the tensor pipe)
#pragma unroll
        for (int ks = 0; ks < 4; ks++) {
            uint32_t a0 = ph[2 * ks][0];
            uint32_t a1 = ph[2 * ks][1];
            uint32_t a2 = ph[2 * ks + 1][0];
            uint32_t a3 = ph[2 * ks + 1][1];
            MMA16(lacc[0], lacc[1], lacc[2], lacc[3],
                  a0, a1, a2, a3, H2_ONE, H2_ONE);
#pragma unroll
            for (int nt2 = 0; nt2 < 16; nt2 += 2) {
                uint32_t b0, b1, b2, b3;
                uint32_t vd = sptr(&Vs[(nt2 * 8 + l16) * PVT + ks * 16 + lh]);
                LDSM_X4(b0, b1, b2, b3, vd);
                MMA16(O[nt2][0], O[nt2][1], O[nt2][2], O[nt2][3],
                      a0, a1, a2, a3, b0, b2);
                MMA16(O[nt2 + 1][0], O[nt2 + 1][1], O[nt2 + 1][2], O[nt2 + 1][3],
                      a0, a1, a2, a3, b1, b3);
            }
        }
    }

    // ---- epilogue (lacc[0]=row lr sum, lacc[2]=row lr+8 sum)
    const int lr = lane >> 2, lc = lane & 3;
    float i0 = 1.0f / lacc[0], i1 = 1.0f / lacc[2];
    const int row0 = m0 + rb + lr;
#pragma unroll
    for (int nt2 = 0; nt2 < 16; nt2++) {
        int col = h * HD + nt2 * 8 + 2 * lc;
        *(uint32_t*)&g_O[(size_t)row0 * DM + col] =
            pack_h2(O[nt2][0] * i0, O[nt2][1] * i0);
        *(uint32_t*)&g_O[(size_t)(row0 + 8) * DM + col] =
            pack_h2(O[nt2][2] * i1, O[nt2][3] * i1);
    }
}

// ---- output projections ------------------------------------------------------
__global__ __launch_bounds__(256, 2) void k_outproj(
    const float* __restrict__ b_out, const float* __restrict__ b_ao,
    float* __restrict__ outbuf)
{
    const int n0 = blockIdx.x * 128;
    const int m0 = blockIdx.y * 128;
    const bool is_enc = (m0 < STXT);
    const __half* B = g_Wt + (size_t)(is_enc ? 7 : 6) * DM * DM + (size_t)n0 * DM;
    const float* bias = (is_enc ? b_ao : b_out) + n0;
    float* out = is_enc ? (outbuf + (size_t)SIMG * DM + (size_t)m0 * DM)
                        : (outbuf + (size_t)(m0 - STXT) * DM);

    float acc[4][4][4];
    gemm_core_h(g_O + (size_t)m0 * DM, B, acc);

    const int tid  = threadIdx.x;
    const int warp = tid >> 5, lane = tid & 31;
    const int wm = (warp >> 2) * 64;
    const int wn = (warp & 3)  * 32;
    const int lr = lane >> 2, lc = lane & 3;

#pragma unroll
    for (int mt = 0; mt < 4; mt++) {
        int row = wm + mt * 16 + lr;
#pragma unroll
        for (int nt = 0; nt < 4; nt++) {
            int col = wn + nt * 8 + 2 * lc;
            float b0 = bias[col];
            float b1 = bias[col + 1];
            float2 lo = make_float2(acc[mt][nt][0] + b0, acc[mt][nt][1] + b1);
            float2 hi = make_float2(acc[mt][nt][2] + b0, acc[mt][nt][3] + b1);
            *(float2*)&out[(size_t)row * DM + n0 + col]       = lo;
            *(float2*)&out[(size_t)(row + 8) * DM + n0 + col] = hi;
        }
    }
}

// ============================================================================
extern "C" void kernel_launch(void* const* d_in, const int* in_sizes, int n_in,
                              void* d_out, int out_size)
{
    const float* hid  = (const float*)d_in[0];
    const float* enc  = (const float*)d_in[1];
    const float* cosb = (const float*)d_in[2];
    const float* sinb = (const float*)d_in[3];
    const float* wq   = (const float*)d_in[4];
    const float* wk   = (const float*)d_in[5];
    const float* wv   = (const float*)d_in[6];
    const float* wqa  = (const float*)d_in[7];
    const float* wka  = (const float*)d_in[8];
    const float* wva  = (const float*)d_in[9];
    const float* bqa  = (const float*)d_in[10];
    const float* bka  = (const float*)d_in[11];
    const float* bva  = (const float*)d_in[12];
    const float* nq   = (const float*)d_in[13];
    const float* nk   = (const float*)d_in[14];
    const float* naq  = (const float*)d_in[15];
    const float* nak  = (const float*)d_in[16];
    const float* wout = (const float*)d_in[17];
    const float* bout = (const float*)d_in[18];
    const float* wao  = (const float*)d_in[19];
    const float* bao  = (const float*)d_in[20];
    float* out = (float*)d_out;

    cudaFuncSetAttribute(k_qkv,     cudaFuncAttributeMaxDynamicSharedMemorySize, GEMM_SMEM);
    cudaFuncSetAttribute(k_outproj, cudaFuncAttributeMaxDynamicSharedMemorySize, GEMM_SMEM);
    cudaFuncSetAttribute(k_flash,   cudaFuncAttributeMaxDynamicSharedMemorySize, FLASH_SMEM);

    k_round_act<<<512, 256>>>(hid, enc);
    dim3 tw_grid(DM / 32, DM / 32, 8);
    k_transw<<<tw_grid, 256>>>(wq, wk, wv, wqa, wka, wva, wout, wao);

    dim3 qkv_grid(DM / 128, S_ALL / 128, 3);        // 24 x 18 x 3
    k_qkv<<<qkv_grid, 256, GEMM_SMEM>>>(bqa, bka, bva,
                                        nq, naq, nk, nak, cosb, sinb);

    dim3 fl_grid(S_ALL / 128, NH);                  // 18 x 24
    k_flash<<<fl_grid, 256, FLASH_SMEM>>>();

    dim3 gemm_grid(DM / 128, S_ALL / 128);          // 24 x 18
    k_outproj<<<gemm_grid, 256, GEMM_SMEM>>>(bout, bao, out);
}